// round 6
// baseline (speedup 1.0000x reference)
#include <cuda_runtime.h>
#include <cstdint>

#define NPTS 16384
#define MCTR 2048

// ---------------- device scratch ----------------
__device__ int    g_bq[4 * MCTR * 64];
__device__ float  g_bufA[50331648];   // up to 96 ch x 524288 cols
__device__ float  g_bufB[67108864];   // up to 128 ch x 524288 cols
__device__ float2 g_part[4096 * 128];
__device__ float  g_a[128];
__device__ float  g_bb[128];

__device__ __forceinline__ float fadd(float a, float b) { return __fadd_rn(a, b); }
__device__ __forceinline__ float fmul(float a, float b) { return __fmul_rn(a, b); }
__device__ __forceinline__ float fsub(float a, float b) { return __fsub_rn(a, b); }

// ============ FPS: 1 CTA/batch, exact arithmetic, first-index argmax ============
__global__ void __launch_bounds__(1024) fps_kernel(const float* __restrict__ xyz,
                                                   float* __restrict__ out)
{
    extern __shared__ float sm[];
    float* sx = sm;
    float* sy = sm + NPTS;
    float* sz = sm + 2 * NPTS;
    __shared__ float rbv[32];
    __shared__ int   rbi[32];
    __shared__ int   s_next;

    const int b = blockIdx.x, tid = threadIdx.x;
    const float* X = xyz + (size_t)b * 3 * NPTS;
    for (int i = tid; i < NPTS; i += 1024) {
        sx[i] = X[i]; sy[i] = X[NPTS + i]; sz[i] = X[2 * NPTS + i];
    }
    float dist[16];
#pragma unroll
    for (int j = 0; j < 16; j++) dist[j] = 1e10f;
    __syncthreads();

    if (tid == 0) {
        out[b * 3 * MCTR + 0] = sx[0];
        out[b * 3 * MCTR + MCTR] = sy[0];
        out[b * 3 * MCTR + 2 * MCTR] = sz[0];
    }
    int last = 0;
    for (int step = 1; step < MCTR; step++) {
        float px = sx[last], py = sy[last], pz = sz[last];
        float bv = -1.0f; int bi = 0;
#pragma unroll
        for (int g = 0; g < 4; g++) {
            int pb = g * 4096 + tid * 4;
            float4 vx = *(const float4*)&sx[pb];
            float4 vy = *(const float4*)&sy[pb];
            float4 vz = *(const float4*)&sz[pb];
            float xs[4] = {vx.x, vx.y, vx.z, vx.w};
            float ys[4] = {vy.x, vy.y, vy.z, vy.w};
            float zs[4] = {vz.x, vz.y, vz.z, vz.w};
#pragma unroll
            for (int e = 0; e < 4; e++) {
                float dx = fsub(xs[e], px), dy = fsub(ys[e], py), dz = fsub(zs[e], pz);
                float d = fadd(fadd(fmul(dx, dx), fmul(dy, dy)), fmul(dz, dz));
                float nd = fminf(dist[g * 4 + e], d);
                dist[g * 4 + e] = nd;
                if (nd > bv) { bv = nd; bi = pb + e; }
            }
        }
#pragma unroll
        for (int off = 16; off > 0; off >>= 1) {
            float ov = __shfl_down_sync(0xffffffffu, bv, off);
            int   oi = __shfl_down_sync(0xffffffffu, bi, off);
            if (ov > bv || (ov == bv && oi < bi)) { bv = ov; bi = oi; }
        }
        if ((tid & 31) == 0) { rbv[tid >> 5] = bv; rbi[tid >> 5] = bi; }
        __syncthreads();
        if (tid < 32) {
            bv = rbv[tid]; bi = rbi[tid];
#pragma unroll
            for (int off = 16; off > 0; off >>= 1) {
                float ov = __shfl_down_sync(0xffffffffu, bv, off);
                int   oi = __shfl_down_sync(0xffffffffu, bi, off);
                if (ov > bv || (ov == bv && oi < bi)) { bv = ov; bi = oi; }
            }
            if (tid == 0) {
                s_next = bi;
                out[b * 3 * MCTR + step] = sx[bi];
                out[b * 3 * MCTR + MCTR + step] = sy[bi];
                out[b * 3 * MCTR + 2 * MCTR + step] = sz[bi];
            }
        }
        __syncthreads();
        last = s_next;
    }
}

// ============ Ball query: warp/center, first-K ascending, early exit ============
__global__ void __launch_bounds__(256) ballquery_kernel(const float* __restrict__ xyz,
                                                        const float* __restrict__ out,
                                                        int K, float r2)
{
    int warp = (blockIdx.x * blockDim.x + threadIdx.x) >> 5;
    int lane = threadIdx.x & 31;
    int b = warp >> 11, m = warp & (MCTR - 1);
    const float* nx = out + b * 3 * MCTR;
    float cx = nx[m], cy = nx[MCTR + m], cz = nx[2 * MCTR + m];
    float sqc = fadd(fadd(fmul(cx, cx), fmul(cy, cy)), fmul(cz, cz));
    const float* X = xyz + (size_t)b * 3 * NPTS;

    int cnt = 0, firstIdx = 0;
    bool haveFirst = false;
    int* dst = g_bq + (size_t)warp * K;
    for (int base = 0; base < NPTS; base += 32) {
        int n = base + lane;
        float x = X[n], y = X[NPTS + n], z = X[2 * NPTS + n];
        float sqx = fadd(fadd(fmul(x, x), fmul(y, y)), fmul(z, z));
        float dot = fadd(fadd(fmul(cx, x), fmul(cy, y)), fmul(cz, z));
        float d2 = fsub(fadd(sqc, sqx), fmul(2.0f, dot));
        bool pred = d2 < r2;
        unsigned msk = __ballot_sync(0xffffffffu, pred);
        if (!haveFirst && msk) { firstIdx = base + __ffs(msk) - 1; haveFirst = true; }
        if (pred) {
            int pos = cnt + __popc(msk & ((1u << lane) - 1u));
            if (pos < K) dst[pos] = n;
        }
        cnt += __popc(msk);
        if (cnt >= K) break;
    }
    if (cnt < K) {
        int fill = haveFirst ? firstIdx : 0;
        for (int p = cnt + lane; p < K; p += 32) dst[p] = fill;
    }
}

// ============ Gather: build X0[c][col] = concat(gxyz - center, gfeat) ============
__global__ void __launch_bounds__(256) gather_kernel(const float* __restrict__ xyz,
                                                     const float* __restrict__ feat,
                                                     const float* __restrict__ out,
                                                     int logK, int cols)
{
    int col = blockIdx.x * 256 + threadIdx.x;
    int n  = g_bq[col];
    int mg = col >> logK;
    int b  = mg >> 11, m = mg & (MCTR - 1);
    const float* Xp = xyz + (size_t)b * 3 * NPTS;
    const float* C  = out + b * 3 * MCTR;
#pragma unroll
    for (int c = 0; c < 3; c++)
        g_bufA[(size_t)c * cols + col] = Xp[c * NPTS + n] - C[c * MCTR + m];
    const float* F = feat + (size_t)b * 64 * NPTS;
    for (int c = 0; c < 64; c++)
        g_bufA[(size_t)(3 + c) * cols + col] = F[(size_t)c * NPTS + n];
}

// ============ GEMM: Y[o][col] = W[o][:] . X[:][col], fused stat partials ============
__global__ void __launch_bounds__(256) gemm_kernel(const float* __restrict__ W,
                                                   const float* __restrict__ X,
                                                   float* __restrict__ Y,
                                                   int Cin, int Cout, int ldc)
{
    __shared__ __align__(16) float Xs[16][132];
    __shared__ __align__(16) float Ws[16][132];
    int tid = threadIdx.x;
    int colBase = blockIdx.x * 128;
    float acc[8][8] = {};
    int nCh = (Cin + 15) >> 4;
    for (int ch = 0; ch < nCh; ch++) {
        int c0 = ch * 16;
        for (int t = tid; t < 2048; t += 256) {
            int o = t & 127, kc = t >> 7, c = c0 + kc;
            Ws[kc][o] = (o < Cout && c < Cin) ? W[o * Cin + c] : 0.f;
        }
        for (int t = tid; t < 2048; t += 256) {
            int j = t & 127, kc = t >> 7, c = c0 + kc;
            Xs[kc][j] = (c < Cin) ? X[(size_t)c * ldc + colBase + j] : 0.f;
        }
        __syncthreads();
        int j4 = (tid & 15) * 4, o8 = (tid >> 4) * 8;
#pragma unroll
        for (int kc = 0; kc < 16; kc++) {
            float4 xa = *(float4*)&Xs[kc][j4];
            float4 xb = *(float4*)&Xs[kc][j4 + 64];
            float4 wa = *(float4*)&Ws[kc][o8];
            float4 wb = *(float4*)&Ws[kc][o8 + 4];
            float xr[8] = {xa.x, xa.y, xa.z, xa.w, xb.x, xb.y, xb.z, xb.w};
            float wr[8] = {wa.x, wa.y, wa.z, wa.w, wb.x, wb.y, wb.z, wb.w};
#pragma unroll
            for (int i = 0; i < 8; i++)
#pragma unroll
                for (int j = 0; j < 8; j++) acc[i][j] = fmaf(wr[i], xr[j], acc[i][j]);
        }
        __syncthreads();
    }
    int o0 = (tid >> 4) * 8, j4 = (tid & 15) * 4;
#pragma unroll
    for (int i = 0; i < 8; i++) {
        int o = o0 + i;
        if (o < Cout) {
            float* dst = Y + (size_t)o * ldc + colBase + j4;
            *(float4*)dst        = make_float4(acc[i][0], acc[i][1], acc[i][2], acc[i][3]);
            *(float4*)(dst + 64) = make_float4(acc[i][4], acc[i][5], acc[i][6], acc[i][7]);
        }
    }
    float s[8], q[8];
#pragma unroll
    for (int i = 0; i < 8; i++) {
        float ts = 0.f, tq = 0.f;
#pragma unroll
        for (int j = 0; j < 8; j++) { ts += acc[i][j]; tq += acc[i][j] * acc[i][j]; }
        s[i] = ts; q[i] = tq;
    }
#pragma unroll
    for (int off = 8; off > 0; off >>= 1)
#pragma unroll
        for (int i = 0; i < 8; i++) {
            s[i] += __shfl_down_sync(0xffffffffu, s[i], off, 16);
            q[i] += __shfl_down_sync(0xffffffffu, q[i], off, 16);
        }
    if ((tid & 15) == 0)
#pragma unroll
        for (int i = 0; i < 8; i++)
            g_part[(size_t)blockIdx.x * 128 + o0 + i] = make_float2(s[i], q[i]);
}

// ============ deterministic stats reduce -> BN scale/shift ============
__global__ void __launch_bounds__(256) reduce_stats_kernel(const float* __restrict__ gam,
                                                           const float* __restrict__ bet,
                                                           int R, float inv_n)
{
    __shared__ float ss[256], sq[256];
    int c = blockIdx.x, tid = threadIdx.x;
    float s = 0.f, q = 0.f;
    for (int r = tid; r < R; r += 256) {
        float2 v = g_part[(size_t)r * 128 + c];
        s += v.x; q += v.y;
    }
    ss[tid] = s; sq[tid] = q;
    __syncthreads();
    for (int off = 128; off > 0; off >>= 1) {
        if (tid < off) { ss[tid] += ss[tid + off]; sq[tid] += sq[tid + off]; }
        __syncthreads();
    }
    if (tid == 0) {
        float mu = ss[0] * inv_n;
        float var = sq[0] * inv_n - mu * mu;
        if (var < 0.f) var = 0.f;
        float a = gam[c] * rsqrtf(var + 1e-5f);
        g_a[c] = a;
        g_bb[c] = bet[c] - mu * a;
    }
}

// ============ in-place BN + ReLU ============
__global__ void __launch_bounds__(1024) apply_kernel(float* __restrict__ Y, int logC)
{
    size_t i = (size_t)blockIdx.x * 1024 + threadIdx.x;
    int c = (int)(i >> logC);
    Y[i] = fmaxf(0.f, fmaf(g_a[c], Y[i], g_bb[c]));
}

// ============ BN + ReLU + max over K -> output features ============
__global__ void __launch_bounds__(1024) maxpool_kernel(const float* __restrict__ Y,
                                                       float* __restrict__ out,
                                                       int K, int chanOff, int ldc)
{
    int gw = (blockIdx.x * 1024 + threadIdx.x) >> 5;
    int lane = threadIdx.x & 31;
    int o = gw & 127;
    int mg = gw >> 7;
    int b = mg >> 11, m = mg & (MCTR - 1);
    float a = g_a[o], bb = g_bb[o];
    const float* src = Y + (size_t)o * ldc + (size_t)mg * K;
    float v = 0.f;
    for (int k = lane; k < K; k += 32)
        v = fmaxf(v, fmaf(a, src[k], bb));
#pragma unroll
    for (int off = 16; off > 0; off >>= 1)
        v = fmaxf(v, __shfl_xor_sync(0xffffffffu, v, off));
    if (lane == 0)
        out[24576 + ((size_t)(b * 256 + chanOff + o)) * MCTR + m] = v;
}

// ==================== host side ====================
extern "C" void kernel_launch(void* const* d_in, const int* in_sizes, int n_in,
                              void* d_out, int out_size)
{
    const float* xyz  = (const float*)d_in[0];
    const float* feat = (const float*)d_in[1];
    // weights: d_in[2 + s*9 + l*3 + {0:w,1:g,2:b}]
    float* out = (float*)d_out;

    cudaFuncSetAttribute(fps_kernel, cudaFuncAttributeMaxDynamicSharedMemorySize, 196608);
    fps_kernel<<<4, 1024, 196608>>>(xyz, out);

    const int KS[2] = {32, 64};
    const float R2[2] = {(float)(0.2 * 0.2), (float)(0.4 * 0.4)};
    const int CH[2][3] = {{64, 64, 128}, {64, 96, 128}};

    for (int s = 0; s < 2; s++) {
        int K = KS[s];
        int logK = (K == 32) ? 5 : 6;
        int cols = 4 * MCTR * K;            // 262144 or 524288
        int logC = (K == 32) ? 18 : 19;
        int nBlk = cols / 128;
        float inv_n = 1.0f / (float)cols;

        ballquery_kernel<<<1024, 256>>>(xyz, out, K, R2[s]);
        gather_kernel<<<cols / 256, 256>>>(xyz, feat, out, logK, cols);

        const float* Wl[3], *Gl[3], *Bl[3];
        for (int l = 0; l < 3; l++) {
            Wl[l] = (const float*)d_in[2 + s * 9 + l * 3 + 0];
            Gl[l] = (const float*)d_in[2 + s * 9 + l * 3 + 1];
            Bl[l] = (const float*)d_in[2 + s * 9 + l * 3 + 2];
        }
        float *pA, *pB;
        cudaGetSymbolAddress((void**)&pA, g_bufA);
        cudaGetSymbolAddress((void**)&pB, g_bufB);

        // L0: A(67) -> B(c0)
        gemm_kernel<<<nBlk, 256>>>(Wl[0], pA, pB, 67, CH[s][0], cols);
        reduce_stats_kernel<<<CH[s][0], 256>>>(Gl[0], Bl[0], nBlk, inv_n);
        apply_kernel<<<(unsigned)(((size_t)CH[s][0] * cols) / 1024), 1024>>>(pB, logC);
        // L1: B -> A(c1)
        gemm_kernel<<<nBlk, 256>>>(Wl[1], pB, pA, CH[s][0], CH[s][1], cols);
        reduce_stats_kernel<<<CH[s][1], 256>>>(Gl[1], Bl[1], nBlk, inv_n);
        apply_kernel<<<(unsigned)(((size_t)CH[s][1] * cols) / 1024), 1024>>>(pA, logC);
        // L2: A -> B(128)
        gemm_kernel<<<nBlk, 256>>>(Wl[2], pA, pB, CH[s][1], CH[s][2], cols);
        reduce_stats_kernel<<<CH[s][2], 256>>>(Gl[2], Bl[2], nBlk, inv_n);
        maxpool_kernel<<<(4 * MCTR * 128) / 32, 1024>>>(pB, out, K, s * 128, cols);
    }
}

// round 7
// speedup vs baseline: 1.2494x; 1.2494x over previous
#include <cuda_runtime.h>
#include <cstdint>

#define NPTS 16384
#define MCTR 2048
#define FPS_CTAS 8
#define FPS_THREADS 256
#define SLICE (NPTS / FPS_CTAS)
#define PPT (SLICE / FPS_THREADS)

// ---------------- device scratch ----------------
__device__ int    g_bq[4 * MCTR * 64];
__device__ float  g_bufA[50331648];   // up to 96 ch x 524288 cols
__device__ float  g_bufB[67108864];   // up to 128 ch x 524288 cols
__device__ float2 g_part[4096 * 128];
__device__ float  g_a[128];
__device__ float  g_bb[128];

__device__ __forceinline__ float fadd(float a, float b) { return __fadd_rn(a, b); }
__device__ __forceinline__ float fmul(float a, float b) { return __fmul_rn(a, b); }
__device__ __forceinline__ float fsub(float a, float b) { return __fsub_rn(a, b); }

// ============ FPS: 8-CTA cluster per batch, register-resident coords ============
__global__ __launch_bounds__(FPS_THREADS) __cluster_dims__(FPS_CTAS, 1, 1)
void fps_cluster_kernel(const float* __restrict__ xyz, float* __restrict__ out)
{
    __shared__ float sx[SLICE], sy[SLICE], sz[SLICE];
    __shared__ float swv[8];
    __shared__ int   swi[8];
    __shared__ __align__(16) float slot[2][8][8];   // [parity][srcRank][v,i,x,y,z,...]

    const int tid = threadIdx.x;
    const int lane = tid & 31, w = tid >> 5;
    const int b = blockIdx.x / FPS_CTAS;
    uint32_t rank;
    asm("mov.u32 %0, %%cluster_ctarank;" : "=r"(rank));
    const float* X = xyz + (size_t)b * 3 * NPTS;
    const int base = rank * SLICE;

    for (int i = tid; i < SLICE; i += FPS_THREADS) {
        sx[i] = X[base + i];
        sy[i] = X[NPTS + base + i];
        sz[i] = X[2 * NPTS + base + i];
    }
    __syncthreads();

    float xr[PPT], yr[PPT], zr[PPT], dist[PPT];
    const int i0 = tid * PPT;
#pragma unroll
    for (int e = 0; e < PPT; e++) {
        xr[e] = sx[i0 + e]; yr[e] = sy[i0 + e]; zr[e] = sz[i0 + e];
        dist[e] = 1e10f;
    }
    float px = X[0], py = X[NPTS], pz = X[2 * NPTS];
    if (rank == 0 && tid == 0) {
        out[b * 3 * MCTR] = px;
        out[b * 3 * MCTR + MCTR] = py;
        out[b * 3 * MCTR + 2 * MCTR] = pz;
    }
    const uint32_t slotBase = (uint32_t)__cvta_generic_to_shared(&slot[0][0][0]);
    int p = 0;

    for (int step = 1; step < MCTR; step++) {
        float bv = -1.f; int bi = 0;
#pragma unroll
        for (int e = 0; e < PPT; e++) {
            float dx = fsub(xr[e], px), dy = fsub(yr[e], py), dz = fsub(zr[e], pz);
            float d  = fadd(fadd(fmul(dx, dx), fmul(dy, dy)), fmul(dz, dz));
            float nd = fminf(dist[e], d);
            dist[e] = nd;
            if (nd > bv) { bv = nd; bi = base + i0 + e; }
        }
#pragma unroll
        for (int off = 16; off > 0; off >>= 1) {
            float ov = __shfl_down_sync(0xffffffffu, bv, off);
            int   oi = __shfl_down_sync(0xffffffffu, bi, off);
            if (ov > bv || (ov == bv && oi < bi)) { bv = ov; bi = oi; }
        }
        if (lane == 0) { swv[w] = bv; swi[w] = bi; }
        __syncthreads();

        if (w == 0) {
            float v = (lane < 8) ? swv[lane] : -2.f;
            int   i = (lane < 8) ? swi[lane] : 0x7fffffff;
#pragma unroll
            for (int off = 4; off > 0; off >>= 1) {
                float ov = __shfl_xor_sync(0xffffffffu, v, off, 8);
                int   oi = __shfl_xor_sync(0xffffffffu, i, off, 8);
                if (ov > v || (ov == v && oi < i)) { v = ov; i = oi; }
            }
            float cx = 0.f, cy = 0.f, cz = 0.f;
            if (lane == 0) { int li = i - base; cx = sx[li]; cy = sy[li]; cz = sz[li]; }
            v  = __shfl_sync(0xffffffffu, v, 0);
            i  = __shfl_sync(0xffffffffu, i, 0);
            cx = __shfl_sync(0xffffffffu, cx, 0);
            cy = __shfl_sync(0xffffffffu, cy, 0);
            cz = __shfl_sync(0xffffffffu, cz, 0);
            if (lane < FPS_CTAS) {
                uint32_t laddr = slotBase + (uint32_t)((p * 8 + (int)rank) * 32);
                uint32_t raddr;
                asm volatile("mapa.shared::cluster.u32 %0, %1, %2;"
                             : "=r"(raddr) : "r"(laddr), "r"(lane));
                asm volatile("st.shared::cluster.b32 [%0], %1;"    :: "r"(raddr), "r"(__float_as_uint(v)) : "memory");
                asm volatile("st.shared::cluster.b32 [%0+4], %1;"  :: "r"(raddr), "r"(i) : "memory");
                asm volatile("st.shared::cluster.b32 [%0+8], %1;"  :: "r"(raddr), "r"(__float_as_uint(cx)) : "memory");
                asm volatile("st.shared::cluster.b32 [%0+12], %1;" :: "r"(raddr), "r"(__float_as_uint(cy)) : "memory");
                asm volatile("st.shared::cluster.b32 [%0+16], %1;" :: "r"(raddr), "r"(__float_as_uint(cz)) : "memory");
            }
        }
        asm volatile("barrier.cluster.arrive.aligned;" ::: "memory");
        asm volatile("barrier.cluster.wait.aligned;" ::: "memory");
        {
            int rl = lane & 7;
            const float* sp = &slot[p][rl][0];
            float v = sp[0];
            int   i = __float_as_int(sp[1]);
            float x = sp[2], y = sp[3], z = sp[4];
#pragma unroll
            for (int off = 4; off > 0; off >>= 1) {
                float ov = __shfl_xor_sync(0xffffffffu, v, off, 8);
                int   oi = __shfl_xor_sync(0xffffffffu, i, off, 8);
                float ox = __shfl_xor_sync(0xffffffffu, x, off, 8);
                float oy = __shfl_xor_sync(0xffffffffu, y, off, 8);
                float oz = __shfl_xor_sync(0xffffffffu, z, off, 8);
                if (ov > v || (ov == v && oi < i)) { v = ov; i = oi; x = ox; y = oy; z = oz; }
            }
            px = x; py = y; pz = z;
            if (rank == 0 && tid == 0) {
                out[b * 3 * MCTR + step] = x;
                out[b * 3 * MCTR + MCTR + step] = y;
                out[b * 3 * MCTR + 2 * MCTR + step] = z;
            }
        }
        p ^= 1;
    }
}

// ============ Ball query: warp/center, first-K ascending, early exit ============
__global__ void __launch_bounds__(256) ballquery_kernel(const float* __restrict__ xyz,
                                                        const float* __restrict__ out,
                                                        int K, float r2)
{
    int warp = (blockIdx.x * blockDim.x + threadIdx.x) >> 5;
    int lane = threadIdx.x & 31;
    int b = warp >> 11, m = warp & (MCTR - 1);
    const float* nx = out + b * 3 * MCTR;
    float cx = nx[m], cy = nx[MCTR + m], cz = nx[2 * MCTR + m];
    float sqc = fadd(fadd(fmul(cx, cx), fmul(cy, cy)), fmul(cz, cz));
    const float* X = xyz + (size_t)b * 3 * NPTS;

    int cnt = 0, firstIdx = 0;
    bool haveFirst = false;
    int* dst = g_bq + (size_t)warp * K;
    for (int base = 0; base < NPTS; base += 32) {
        int n = base + lane;
        float x = X[n], y = X[NPTS + n], z = X[2 * NPTS + n];
        float sqx = fadd(fadd(fmul(x, x), fmul(y, y)), fmul(z, z));
        float dot = fadd(fadd(fmul(cx, x), fmul(cy, y)), fmul(cz, z));
        float d2 = fsub(fadd(sqc, sqx), fmul(2.0f, dot));
        bool pred = d2 < r2;
        unsigned msk = __ballot_sync(0xffffffffu, pred);
        if (!haveFirst && msk) { firstIdx = base + __ffs(msk) - 1; haveFirst = true; }
        if (pred) {
            int pos = cnt + __popc(msk & ((1u << lane) - 1u));
            if (pos < K) dst[pos] = n;
        }
        cnt += __popc(msk);
        if (cnt >= K) break;
    }
    if (cnt < K) {
        int fill = haveFirst ? firstIdx : 0;
        for (int p = cnt + lane; p < K; p += 32) dst[p] = fill;
    }
}

// ============ Gather: build X0[c][col] = concat(gxyz - center, gfeat) ============
__global__ void __launch_bounds__(256) gather_kernel(const float* __restrict__ xyz,
                                                     const float* __restrict__ feat,
                                                     const float* __restrict__ out,
                                                     int logK, int cols)
{
    int col = blockIdx.x * 256 + threadIdx.x;
    int n  = g_bq[col];
    int mg = col >> logK;
    int b  = mg >> 11, m = mg & (MCTR - 1);
    const float* Xp = xyz + (size_t)b * 3 * NPTS;
    const float* C  = out + b * 3 * MCTR;
#pragma unroll
    for (int c = 0; c < 3; c++)
        g_bufA[(size_t)c * cols + col] = Xp[c * NPTS + n] - C[c * MCTR + m];
    const float* F = feat + (size_t)b * 64 * NPTS;
    for (int c = 0; c < 64; c++)
        g_bufA[(size_t)(3 + c) * cols + col] = F[(size_t)c * NPTS + n];
}

// ============ GEMM: Y[o][col] = W[o][:] . X[:][col], fused stat partials ============
__global__ void __launch_bounds__(256) gemm_kernel(const float* __restrict__ W,
                                                   const float* __restrict__ X,
                                                   float* __restrict__ Y,
                                                   int Cin, int Cout, int ldc)
{
    __shared__ __align__(16) float Xs[16][132];
    __shared__ __align__(16) float Ws[16][132];
    int tid = threadIdx.x;
    int colBase = blockIdx.x * 128;
    float acc[8][8] = {};
    int nCh = (Cin + 15) >> 4;
    for (int ch = 0; ch < nCh; ch++) {
        int c0 = ch * 16;
        for (int t = tid; t < 2048; t += 256) {
            int o = t & 127, kc = t >> 7, c = c0 + kc;
            Ws[kc][o] = (o < Cout && c < Cin) ? W[o * Cin + c] : 0.f;
        }
        for (int t = tid; t < 2048; t += 256) {
            int j = t & 127, kc = t >> 7, c = c0 + kc;
            Xs[kc][j] = (c < Cin) ? X[(size_t)c * ldc + colBase + j] : 0.f;
        }
        __syncthreads();
        int j4 = (tid & 15) * 4, o8 = (tid >> 4) * 8;
#pragma unroll
        for (int kc = 0; kc < 16; kc++) {
            float4 xa = *(float4*)&Xs[kc][j4];
            float4 xb = *(float4*)&Xs[kc][j4 + 64];
            float4 wa = *(float4*)&Ws[kc][o8];
            float4 wb = *(float4*)&Ws[kc][o8 + 4];
            float xr[8] = {xa.x, xa.y, xa.z, xa.w, xb.x, xb.y, xb.z, xb.w};
            float wr[8] = {wa.x, wa.y, wa.z, wa.w, wb.x, wb.y, wb.z, wb.w};
#pragma unroll
            for (int i = 0; i < 8; i++)
#pragma unroll
                for (int j = 0; j < 8; j++) acc[i][j] = fmaf(wr[i], xr[j], acc[i][j]);
        }
        __syncthreads();
    }
    int o0 = (tid >> 4) * 8, j4 = (tid & 15) * 4;
#pragma unroll
    for (int i = 0; i < 8; i++) {
        int o = o0 + i;
        if (o < Cout) {
            float* dst = Y + (size_t)o * ldc + colBase + j4;
            *(float4*)dst        = make_float4(acc[i][0], acc[i][1], acc[i][2], acc[i][3]);
            *(float4*)(dst + 64) = make_float4(acc[i][4], acc[i][5], acc[i][6], acc[i][7]);
        }
    }
    float s[8], q[8];
#pragma unroll
    for (int i = 0; i < 8; i++) {
        float ts = 0.f, tq = 0.f;
#pragma unroll
        for (int j = 0; j < 8; j++) { ts += acc[i][j]; tq += acc[i][j] * acc[i][j]; }
        s[i] = ts; q[i] = tq;
    }
#pragma unroll
    for (int off = 8; off > 0; off >>= 1)
#pragma unroll
        for (int i = 0; i < 8; i++) {
            s[i] += __shfl_down_sync(0xffffffffu, s[i], off, 16);
            q[i] += __shfl_down_sync(0xffffffffu, q[i], off, 16);
        }
    if ((tid & 15) == 0)
#pragma unroll
        for (int i = 0; i < 8; i++)
            g_part[(size_t)blockIdx.x * 128 + o0 + i] = make_float2(s[i], q[i]);
}

// ============ deterministic stats reduce -> BN scale/shift ============
__global__ void __launch_bounds__(256) reduce_stats_kernel(const float* __restrict__ gam,
                                                           const float* __restrict__ bet,
                                                           int R, float inv_n)
{
    __shared__ float ss[256], sq[256];
    int c = blockIdx.x, tid = threadIdx.x;
    float s = 0.f, q = 0.f;
    for (int r = tid; r < R; r += 256) {
        float2 v = g_part[(size_t)r * 128 + c];
        s += v.x; q += v.y;
    }
    ss[tid] = s; sq[tid] = q;
    __syncthreads();
    for (int off = 128; off > 0; off >>= 1) {
        if (tid < off) { ss[tid] += ss[tid + off]; sq[tid] += sq[tid + off]; }
        __syncthreads();
    }
    if (tid == 0) {
        float mu = ss[0] * inv_n;
        float var = sq[0] * inv_n - mu * mu;
        if (var < 0.f) var = 0.f;
        float a = gam[c] * rsqrtf(var + 1e-5f);
        g_a[c] = a;
        g_bb[c] = bet[c] - mu * a;
    }
}

// ============ in-place BN + ReLU ============
__global__ void __launch_bounds__(1024) apply_kernel(float* __restrict__ Y, int logC)
{
    size_t i = (size_t)blockIdx.x * 1024 + threadIdx.x;
    int c = (int)(i >> logC);
    Y[i] = fmaxf(0.f, fmaf(g_a[c], Y[i], g_bb[c]));
}

// ============ BN + ReLU + max over K -> output features ============
__global__ void __launch_bounds__(1024) maxpool_kernel(const float* __restrict__ Y,
                                                       float* __restrict__ out,
                                                       int K, int chanOff, int ldc)
{
    int gw = (blockIdx.x * 1024 + threadIdx.x) >> 5;
    int lane = threadIdx.x & 31;
    int o = gw & 127;
    int mg = gw >> 7;
    int b = mg >> 11, m = mg & (MCTR - 1);
    float a = g_a[o], bb = g_bb[o];
    const float* src = Y + (size_t)o * ldc + (size_t)mg * K;
    float v = 0.f;
    for (int k = lane; k < K; k += 32)
        v = fmaxf(v, fmaf(a, src[k], bb));
#pragma unroll
    for (int off = 16; off > 0; off >>= 1)
        v = fmaxf(v, __shfl_xor_sync(0xffffffffu, v, off));
    if (lane == 0)
        out[24576 + ((size_t)(b * 256 + chanOff + o)) * MCTR + m] = v;
}

// ==================== host side ====================
extern "C" void kernel_launch(void* const* d_in, const int* in_sizes, int n_in,
                              void* d_out, int out_size)
{
    const float* xyz  = (const float*)d_in[0];
    const float* feat = (const float*)d_in[1];
    float* out = (float*)d_out;

    fps_cluster_kernel<<<4 * FPS_CTAS, FPS_THREADS>>>(xyz, out);

    const int KS[2] = {32, 64};
    const float R2[2] = {(float)(0.2 * 0.2), (float)(0.4 * 0.4)};
    const int CH[2][3] = {{64, 64, 128}, {64, 96, 128}};

    for (int s = 0; s < 2; s++) {
        int K = KS[s];
        int logK = (K == 32) ? 5 : 6;
        int cols = 4 * MCTR * K;            // 262144 or 524288
        int logC = (K == 32) ? 18 : 19;
        int nBlk = cols / 128;
        float inv_n = 1.0f / (float)cols;

        ballquery_kernel<<<1024, 256>>>(xyz, out, K, R2[s]);
        gather_kernel<<<cols / 256, 256>>>(xyz, feat, out, logK, cols);

        const float* Wl[3], *Gl[3], *Bl[3];
        for (int l = 0; l < 3; l++) {
            Wl[l] = (const float*)d_in[2 + s * 9 + l * 3 + 0];
            Gl[l] = (const float*)d_in[2 + s * 9 + l * 3 + 1];
            Bl[l] = (const float*)d_in[2 + s * 9 + l * 3 + 2];
        }
        float *pA, *pB;
        cudaGetSymbolAddress((void**)&pA, g_bufA);
        cudaGetSymbolAddress((void**)&pB, g_bufB);

        // L0: A(67) -> B(c0)
        gemm_kernel<<<nBlk, 256>>>(Wl[0], pA, pB, 67, CH[s][0], cols);
        reduce_stats_kernel<<<CH[s][0], 256>>>(Gl[0], Bl[0], nBlk, inv_n);
        apply_kernel<<<(unsigned)(((size_t)CH[s][0] * cols) / 1024), 1024>>>(pB, logC);
        // L1: B -> A(c1)
        gemm_kernel<<<nBlk, 256>>>(Wl[1], pB, pA, CH[s][0], CH[s][1], cols);
        reduce_stats_kernel<<<CH[s][1], 256>>>(Gl[1], Bl[1], nBlk, inv_n);
        apply_kernel<<<(unsigned)(((size_t)CH[s][1] * cols) / 1024), 1024>>>(pA, logC);
        // L2: A -> B(128)
        gemm_kernel<<<nBlk, 256>>>(Wl[2], pA, pB, CH[s][1], CH[s][2], cols);
        reduce_stats_kernel<<<CH[s][2], 256>>>(Gl[2], Bl[2], nBlk, inv_n);
        maxpool_kernel<<<(4 * MCTR * 128) / 32, 1024>>>(pB, out, K, s * 128, cols);
    }
}

// round 8
// speedup vs baseline: 1.2896x; 1.0322x over previous
#include <cuda_runtime.h>
#include <cstdint>

#define NPTS 16384
#define MCTR 2048
#define FPS_CTAS 8
#define FPS_THREADS 256
#define SLICE (NPTS / FPS_CTAS)
#define PPT (SLICE / FPS_THREADS)

// ---------------- device scratch ----------------
__device__ int    g_bq[4 * MCTR * 64];
__device__ float  g_bufA[50331648];   // up to 96 ch x 524288 cols
__device__ float  g_bufB[67108864];   // up to 128 ch x 524288 cols
__device__ float2 g_part[4096 * 128];
__device__ float  g_a[128];
__device__ float  g_bb[128];

__device__ __forceinline__ float fadd(float a, float b) { return __fadd_rn(a, b); }
__device__ __forceinline__ float fmul(float a, float b) { return __fmul_rn(a, b); }
__device__ __forceinline__ float fsub(float a, float b) { return __fsub_rn(a, b); }

// ============ FPS: 8-CTA cluster per batch, register-resident coords ============
__global__ __launch_bounds__(FPS_THREADS) __cluster_dims__(FPS_CTAS, 1, 1)
void fps_cluster_kernel(const float* __restrict__ xyz, float* __restrict__ out)
{
    __shared__ float sx[SLICE], sy[SLICE], sz[SLICE];
    __shared__ float swv[8];
    __shared__ int   swi[8];
    __shared__ __align__(16) float slot[2][8][8];   // [parity][srcRank][v,i,x,y,z,...]

    const int tid = threadIdx.x;
    const int lane = tid & 31, w = tid >> 5;
    const int b = blockIdx.x / FPS_CTAS;
    uint32_t rank;
    asm("mov.u32 %0, %%cluster_ctarank;" : "=r"(rank));
    const float* X = xyz + (size_t)b * 3 * NPTS;
    const int base = rank * SLICE;

    for (int i = tid; i < SLICE; i += FPS_THREADS) {
        sx[i] = X[base + i];
        sy[i] = X[NPTS + base + i];
        sz[i] = X[2 * NPTS + base + i];
    }
    __syncthreads();

    float xr[PPT], yr[PPT], zr[PPT], dist[PPT];
    const int i0 = tid * PPT;
#pragma unroll
    for (int e = 0; e < PPT; e++) {
        xr[e] = sx[i0 + e]; yr[e] = sy[i0 + e]; zr[e] = sz[i0 + e];
        dist[e] = 1e10f;
    }
    float px = X[0], py = X[NPTS], pz = X[2 * NPTS];
    if (rank == 0 && tid == 0) {
        out[b * 3 * MCTR] = px;
        out[b * 3 * MCTR + MCTR] = py;
        out[b * 3 * MCTR + 2 * MCTR] = pz;
    }
    const uint32_t slotBase = (uint32_t)__cvta_generic_to_shared(&slot[0][0][0]);
    int p = 0;

    for (int step = 1; step < MCTR; step++) {
        float bv = -1.f; int bi = 0;
#pragma unroll
        for (int e = 0; e < PPT; e++) {
            float dx = fsub(xr[e], px), dy = fsub(yr[e], py), dz = fsub(zr[e], pz);
            float d  = fadd(fadd(fmul(dx, dx), fmul(dy, dy)), fmul(dz, dz));
            float nd = fminf(dist[e], d);
            dist[e] = nd;
            if (nd > bv) { bv = nd; bi = base + i0 + e; }
        }
#pragma unroll
        for (int off = 16; off > 0; off >>= 1) {
            float ov = __shfl_down_sync(0xffffffffu, bv, off);
            int   oi = __shfl_down_sync(0xffffffffu, bi, off);
            if (ov > bv || (ov == bv && oi < bi)) { bv = ov; bi = oi; }
        }
        if (lane == 0) { swv[w] = bv; swi[w] = bi; }
        __syncthreads();

        if (w == 0) {
            float v = (lane < 8) ? swv[lane] : -2.f;
            int   i = (lane < 8) ? swi[lane] : 0x7fffffff;
#pragma unroll
            for (int off = 4; off > 0; off >>= 1) {
                float ov = __shfl_xor_sync(0xffffffffu, v, off, 8);
                int   oi = __shfl_xor_sync(0xffffffffu, i, off, 8);
                if (ov > v || (ov == v && oi < i)) { v = ov; i = oi; }
            }
            float cx = 0.f, cy = 0.f, cz = 0.f;
            if (lane == 0) { int li = i - base; cx = sx[li]; cy = sy[li]; cz = sz[li]; }
            v  = __shfl_sync(0xffffffffu, v, 0);
            i  = __shfl_sync(0xffffffffu, i, 0);
            cx = __shfl_sync(0xffffffffu, cx, 0);
            cy = __shfl_sync(0xffffffffu, cy, 0);
            cz = __shfl_sync(0xffffffffu, cz, 0);
            if (lane < FPS_CTAS) {
                uint32_t laddr = slotBase + (uint32_t)((p * 8 + (int)rank) * 32);
                uint32_t raddr;
                asm volatile("mapa.shared::cluster.u32 %0, %1, %2;"
                             : "=r"(raddr) : "r"(laddr), "r"(lane));
                asm volatile("st.shared::cluster.b32 [%0], %1;"    :: "r"(raddr), "r"(__float_as_uint(v)) : "memory");
                asm volatile("st.shared::cluster.b32 [%0+4], %1;"  :: "r"(raddr), "r"(i) : "memory");
                asm volatile("st.shared::cluster.b32 [%0+8], %1;"  :: "r"(raddr), "r"(__float_as_uint(cx)) : "memory");
                asm volatile("st.shared::cluster.b32 [%0+12], %1;" :: "r"(raddr), "r"(__float_as_uint(cy)) : "memory");
                asm volatile("st.shared::cluster.b32 [%0+16], %1;" :: "r"(raddr), "r"(__float_as_uint(cz)) : "memory");
            }
        }
        asm volatile("barrier.cluster.arrive.aligned;" ::: "memory");
        asm volatile("barrier.cluster.wait.aligned;" ::: "memory");
        {
            int rl = lane & 7;
            const float* sp = &slot[p][rl][0];
            float v = sp[0];
            int   i = __float_as_int(sp[1]);
            float x = sp[2], y = sp[3], z = sp[4];
#pragma unroll
            for (int off = 4; off > 0; off >>= 1) {
                float ov = __shfl_xor_sync(0xffffffffu, v, off, 8);
                int   oi = __shfl_xor_sync(0xffffffffu, i, off, 8);
                float ox = __shfl_xor_sync(0xffffffffu, x, off, 8);
                float oy = __shfl_xor_sync(0xffffffffu, y, off, 8);
                float oz = __shfl_xor_sync(0xffffffffu, z, off, 8);
                if (ov > v || (ov == v && oi < i)) { v = ov; i = oi; x = ox; y = oy; z = oz; }
            }
            px = x; py = y; pz = z;
            if (rank == 0 && tid == 0) {
                out[b * 3 * MCTR + step] = x;
                out[b * 3 * MCTR + MCTR + step] = y;
                out[b * 3 * MCTR + 2 * MCTR + step] = z;
            }
        }
        p ^= 1;
    }
}

// ============ Ball query: warp/center, first-K ascending, early exit ============
__global__ void __launch_bounds__(256) ballquery_kernel(const float* __restrict__ xyz,
                                                        const float* __restrict__ out,
                                                        int K, float r2)
{
    int warp = (blockIdx.x * blockDim.x + threadIdx.x) >> 5;
    int lane = threadIdx.x & 31;
    int b = warp >> 11, m = warp & (MCTR - 1);
    const float* nx = out + b * 3 * MCTR;
    float cx = nx[m], cy = nx[MCTR + m], cz = nx[2 * MCTR + m];
    float sqc = fadd(fadd(fmul(cx, cx), fmul(cy, cy)), fmul(cz, cz));
    const float* X = xyz + (size_t)b * 3 * NPTS;

    int cnt = 0, firstIdx = 0;
    bool haveFirst = false;
    int* dst = g_bq + (size_t)warp * K;
    for (int base = 0; base < NPTS; base += 32) {
        int n = base + lane;
        float x = X[n], y = X[NPTS + n], z = X[2 * NPTS + n];
        float sqx = fadd(fadd(fmul(x, x), fmul(y, y)), fmul(z, z));
        float dot = fadd(fadd(fmul(cx, x), fmul(cy, y)), fmul(cz, z));
        float d2 = fsub(fadd(sqc, sqx), fmul(2.0f, dot));
        bool pred = d2 < r2;
        unsigned msk = __ballot_sync(0xffffffffu, pred);
        if (!haveFirst && msk) { firstIdx = base + __ffs(msk) - 1; haveFirst = true; }
        if (pred) {
            int pos = cnt + __popc(msk & ((1u << lane) - 1u));
            if (pos < K) dst[pos] = n;
        }
        cnt += __popc(msk);
        if (cnt >= K) break;
    }
    if (cnt < K) {
        int fill = haveFirst ? firstIdx : 0;
        for (int p = cnt + lane; p < K; p += 32) dst[p] = fill;
    }
}

// ============ Gather: build X0[c][col] = concat(gxyz - center, gfeat) ============
__global__ void __launch_bounds__(256) gather_kernel(const float* __restrict__ xyz,
                                                     const float* __restrict__ feat,
                                                     const float* __restrict__ out,
                                                     int logK, int cols)
{
    int col = blockIdx.x * 256 + threadIdx.x;
    int n  = g_bq[col];
    int mg = col >> logK;
    int b  = mg >> 11, m = mg & (MCTR - 1);
    const float* Xp = xyz + (size_t)b * 3 * NPTS;
    const float* C  = out + b * 3 * MCTR;
#pragma unroll
    for (int c = 0; c < 3; c++)
        g_bufA[(size_t)c * cols + col] = Xp[c * NPTS + n] - C[c * MCTR + m];
    const float* F = feat + (size_t)b * 64 * NPTS;
    for (int c = 0; c < 64; c++)
        g_bufA[(size_t)(3 + c) * cols + col] = F[(size_t)c * NPTS + n];
}

// ============ GEMM: Y[o][col] = W[o][:] . X'[:][col]  with X' = BN?relu(bn(X)):X
//              double-buffered smem pipeline, fused stat partials ============
template <bool BN>
__global__ void __launch_bounds__(256, 2) gemm_kernel(const float* __restrict__ W,
                                                      const float* __restrict__ X,
                                                      float* __restrict__ Y,
                                                      int Cin, int Cout, int ldc)
{
    __shared__ __align__(16) float Xs[2][16][132];
    __shared__ __align__(16) float Ws[2][16][132];
    __shared__ float sa[128], sb[128];
    const int tid = threadIdx.x;
    const int colBase = blockIdx.x * 128;

    if (BN && tid < Cin) { sa[tid] = g_a[tid]; sb[tid] = g_bb[tid]; }
    __syncthreads();

    const int nCh = (Cin + 15) >> 4;
    float rx[8], rw[8];

    // staging map: element k of this thread -> idx = tid + k*256 ; j=idx&127, kc=idx>>7
    auto loadT = [&](int c0, float* prx, float* prw) {
#pragma unroll
        for (int k = 0; k < 8; k++) {
            int idx = tid + k * 256;
            int j = idx & 127, kc = idx >> 7;
            int c = c0 + kc;
            float xv = 0.f;
            if (c < Cin) {
                xv = X[(size_t)c * ldc + colBase + j];
                if (BN) xv = fmaxf(0.f, fmaf(sa[c], xv, sb[c]));
            }
            prx[k] = xv;
            prw[k] = (j < Cout && c < Cin) ? W[j * Cin + c] : 0.f;
        }
    };
    auto storeT = [&](int buf, const float* prx, const float* prw) {
#pragma unroll
        for (int k = 0; k < 8; k++) {
            int idx = tid + k * 256;
            int j = idx & 127, kc = idx >> 7;
            Xs[buf][kc][j] = prx[k];
            Ws[buf][kc][j] = prw[k];
        }
    };

    loadT(0, rx, rw);
    storeT(0, rx, rw);
    __syncthreads();

    float acc[8][8] = {};
    const int j4 = (tid & 15) * 4, o8 = (tid >> 4) * 8;

    for (int ch = 0; ch < nCh; ch++) {
        const int buf = ch & 1;
        if (ch + 1 < nCh) loadT((ch + 1) * 16, rx, rw);
#pragma unroll
        for (int kc = 0; kc < 16; kc++) {
            float4 xa = *(float4*)&Xs[buf][kc][j4];
            float4 xb = *(float4*)&Xs[buf][kc][j4 + 64];
            float4 wa = *(float4*)&Ws[buf][kc][o8];
            float4 wb = *(float4*)&Ws[buf][kc][o8 + 4];
            float xv[8] = {xa.x, xa.y, xa.z, xa.w, xb.x, xb.y, xb.z, xb.w};
            float wv[8] = {wa.x, wa.y, wa.z, wa.w, wb.x, wb.y, wb.z, wb.w};
#pragma unroll
            for (int i = 0; i < 8; i++)
#pragma unroll
                for (int j = 0; j < 8; j++) acc[i][j] = fmaf(wv[i], xv[j], acc[i][j]);
        }
        if (ch + 1 < nCh) {
            __syncthreads();
            storeT(buf ^ 1, rx, rw);
            __syncthreads();
        }
    }

    const int o0 = o8;
#pragma unroll
    for (int i = 0; i < 8; i++) {
        int o = o0 + i;
        if (o < Cout) {
            float* dst = Y + (size_t)o * ldc + colBase + j4;
            *(float4*)dst        = make_float4(acc[i][0], acc[i][1], acc[i][2], acc[i][3]);
            *(float4*)(dst + 64) = make_float4(acc[i][4], acc[i][5], acc[i][6], acc[i][7]);
        }
    }
    float s[8], q[8];
#pragma unroll
    for (int i = 0; i < 8; i++) {
        float ts = 0.f, tq = 0.f;
#pragma unroll
        for (int j = 0; j < 8; j++) { ts += acc[i][j]; tq += acc[i][j] * acc[i][j]; }
        s[i] = ts; q[i] = tq;
    }
#pragma unroll
    for (int off = 8; off > 0; off >>= 1)
#pragma unroll
        for (int i = 0; i < 8; i++) {
            s[i] += __shfl_down_sync(0xffffffffu, s[i], off, 16);
            q[i] += __shfl_down_sync(0xffffffffu, q[i], off, 16);
        }
    if ((tid & 15) == 0)
#pragma unroll
        for (int i = 0; i < 8; i++)
            g_part[(size_t)blockIdx.x * 128 + o0 + i] = make_float2(s[i], q[i]);
}

// ============ deterministic stats reduce -> BN scale/shift ============
__global__ void __launch_bounds__(256) reduce_stats_kernel(const float* __restrict__ gam,
                                                           const float* __restrict__ bet,
                                                           int R, float inv_n)
{
    __shared__ float ss[256], sq[256];
    int c = blockIdx.x, tid = threadIdx.x;
    float s = 0.f, q = 0.f;
    for (int r = tid; r < R; r += 256) {
        float2 v = g_part[(size_t)r * 128 + c];
        s += v.x; q += v.y;
    }
    ss[tid] = s; sq[tid] = q;
    __syncthreads();
    for (int off = 128; off > 0; off >>= 1) {
        if (tid < off) { ss[tid] += ss[tid + off]; sq[tid] += sq[tid + off]; }
        __syncthreads();
    }
    if (tid == 0) {
        float mu = ss[0] * inv_n;
        float var = sq[0] * inv_n - mu * mu;
        if (var < 0.f) var = 0.f;
        float a = gam[c] * rsqrtf(var + 1e-5f);
        g_a[c] = a;
        g_bb[c] = bet[c] - mu * a;
    }
}

// ============ BN + ReLU + max over K -> output features ============
__global__ void __launch_bounds__(1024) maxpool_kernel(const float* __restrict__ Y,
                                                       float* __restrict__ out,
                                                       int K, int chanOff, int ldc)
{
    int gw = (blockIdx.x * 1024 + threadIdx.x) >> 5;
    int lane = threadIdx.x & 31;
    int o = gw & 127;
    int mg = gw >> 7;
    int b = mg >> 11, m = mg & (MCTR - 1);
    float a = g_a[o], bb = g_bb[o];
    const float* src = Y + (size_t)o * ldc + (size_t)mg * K;
    float v = 0.f;
    for (int k = lane; k < K; k += 32)
        v = fmaxf(v, fmaf(a, src[k], bb));
#pragma unroll
    for (int off = 16; off > 0; off >>= 1)
        v = fmaxf(v, __shfl_xor_sync(0xffffffffu, v, off));
    if (lane == 0)
        out[24576 + ((size_t)(b * 256 + chanOff + o)) * MCTR + m] = v;
}

// ==================== host side ====================
extern "C" void kernel_launch(void* const* d_in, const int* in_sizes, int n_in,
                              void* d_out, int out_size)
{
    const float* xyz  = (const float*)d_in[0];
    const float* feat = (const float*)d_in[1];
    float* out = (float*)d_out;

    fps_cluster_kernel<<<4 * FPS_CTAS, FPS_THREADS>>>(xyz, out);

    const int KS[2] = {32, 64};
    const float R2[2] = {(float)(0.2 * 0.2), (float)(0.4 * 0.4)};
    const int CH[2][3] = {{64, 64, 128}, {64, 96, 128}};

    for (int s = 0; s < 2; s++) {
        int K = KS[s];
        int logK = (K == 32) ? 5 : 6;
        int cols = 4 * MCTR * K;            // 262144 or 524288
        int nBlk = cols / 128;
        float inv_n = 1.0f / (float)cols;

        ballquery_kernel<<<1024, 256>>>(xyz, out, K, R2[s]);
        gather_kernel<<<cols / 256, 256>>>(xyz, feat, out, logK, cols);

        const float* Wl[3], *Gl[3], *Bl[3];
        for (int l = 0; l < 3; l++) {
            Wl[l] = (const float*)d_in[2 + s * 9 + l * 3 + 0];
            Gl[l] = (const float*)d_in[2 + s * 9 + l * 3 + 1];
            Bl[l] = (const float*)d_in[2 + s * 9 + l * 3 + 2];
        }
        float *pA, *pB;
        cudaGetSymbolAddress((void**)&pA, g_bufA);
        cudaGetSymbolAddress((void**)&pB, g_bufB);

        // L0: A(67 raw) -> B(c0)
        gemm_kernel<false><<<nBlk, 256>>>(Wl[0], pA, pB, 67, CH[s][0], cols);
        reduce_stats_kernel<<<CH[s][0], 256>>>(Gl[0], Bl[0], nBlk, inv_n);
        // L1: B (bn+relu fused on load) -> A(c1)
        gemm_kernel<true><<<nBlk, 256>>>(Wl[1], pB, pA, CH[s][0], CH[s][1], cols);
        reduce_stats_kernel<<<CH[s][1], 256>>>(Gl[1], Bl[1], nBlk, inv_n);
        // L2: A (bn+relu fused on load) -> B(128)
        gemm_kernel<true><<<nBlk, 256>>>(Wl[2], pA, pB, CH[s][1], CH[s][2], cols);
        reduce_stats_kernel<<<CH[s][2], 256>>>(Gl[2], Bl[2], nBlk, inv_n);
        maxpool_kernel<<<(4 * MCTR * 128) / 32, 1024>>>(pB, out, K, s * 128, cols);
    }
}

// round 9
// speedup vs baseline: 1.3574x; 1.0525x over previous
#include <cuda_runtime.h>
#include <cstdint>

#define NPTS 16384
#define MCTR 2048
#define FPS_CTAS 8
#define FPS_THREADS 256
#define SLICE (NPTS / FPS_CTAS)
#define PPT (SLICE / FPS_THREADS)

// ---------------- device scratch ----------------
__device__ int    g_bq[4 * MCTR * 64];
__device__ float  g_bufA[50331648];   // up to 96 ch x 524288 cols
__device__ float  g_bufB[67108864];   // up to 128 ch x 524288 cols
__device__ float2 g_part[4096 * 128];
__device__ float  g_a[128];
__device__ float  g_bb[128];

__device__ __forceinline__ float fadd(float a, float b) { return __fadd_rn(a, b); }
__device__ __forceinline__ float fmul(float a, float b) { return __fmul_rn(a, b); }
__device__ __forceinline__ float fsub(float a, float b) { return __fsub_rn(a, b); }

// ---- mbarrier helpers (cluster scope) ----
__device__ __forceinline__ void mbar_init(uint32_t addr, uint32_t count) {
    asm volatile("mbarrier.init.shared.b64 [%0], %1;" :: "r"(addr), "r"(count) : "memory");
}
__device__ __forceinline__ void mbar_wait_cluster(uint32_t addr, uint32_t parity) {
    asm volatile(
        "{\n\t.reg .pred P;\n\t"
        "WAITL_%=:\n\t"
        "mbarrier.try_wait.parity.acquire.cluster.shared::cta.b64 P, [%0], %1, 0x989680;\n\t"
        "@P bra.uni DONEL_%=;\n\t"
        "bra.uni WAITL_%=;\n\t"
        "DONEL_%=:\n\t}"
        :: "r"(addr), "r"(parity) : "memory");
}
__device__ __forceinline__ void mbar_arrive_remote(uint32_t laddr, uint32_t rank) {
    asm volatile(
        "{\n\t.reg .b32 ra;\n\t"
        "mapa.shared::cluster.u32 ra, %0, %1;\n\t"
        "mbarrier.arrive.shared::cluster.b64 _, [ra];\n\t}"
        :: "r"(laddr), "r"(rank) : "memory");
}
__device__ __forceinline__ uint32_t mapa_u32(uint32_t laddr, uint32_t rank) {
    uint32_t ra;
    asm volatile("mapa.shared::cluster.u32 %0, %1, %2;" : "=r"(ra) : "r"(laddr), "r"(rank));
    return ra;
}
__device__ __forceinline__ void st_cluster_b32(uint32_t addr, uint32_t v) {
    asm volatile("st.shared::cluster.b32 [%0], %1;" :: "r"(addr), "r"(v) : "memory");
}

// ============ FPS: 8-CTA cluster per batch, mbarrier leader-reduce exchange ============
__global__ __launch_bounds__(FPS_THREADS) __cluster_dims__(FPS_CTAS, 1, 1)
void fps_cluster_kernel(const float* __restrict__ xyz, float* __restrict__ out)
{
    __shared__ float sx[SLICE], sy[SLICE], sz[SLICE];
    __shared__ float swv[8];
    __shared__ int   swi[8];
    __shared__ __align__(16) float cand[8][8];    // leader: per-rank {v,i,x,y,z}
    __shared__ __align__(16) float res[4];        // winner {x,y,z}
    __shared__ __align__(8) unsigned long long candBar, resBar;

    const int tid = threadIdx.x;
    const int lane = tid & 31, w = tid >> 5;
    const int b = blockIdx.x / FPS_CTAS;
    uint32_t rank;
    asm("mov.u32 %0, %%cluster_ctarank;" : "=r"(rank));
    const float* X = xyz + (size_t)b * 3 * NPTS;
    const int base = rank * SLICE;

    for (int i = tid; i < SLICE; i += FPS_THREADS) {
        sx[i] = X[base + i];
        sy[i] = X[NPTS + base + i];
        sz[i] = X[2 * NPTS + base + i];
    }
    const uint32_t candBase = (uint32_t)__cvta_generic_to_shared(&cand[0][0]);
    const uint32_t resBase  = (uint32_t)__cvta_generic_to_shared(&res[0]);
    const uint32_t candBarA = (uint32_t)__cvta_generic_to_shared(&candBar);
    const uint32_t resBarA  = (uint32_t)__cvta_generic_to_shared(&resBar);
    if (tid == 0) {
        mbar_init(candBarA, FPS_CTAS);
        mbar_init(resBarA, 1);
    }
    __syncthreads();
    asm volatile("barrier.cluster.arrive.aligned;" ::: "memory");
    asm volatile("barrier.cluster.wait.aligned;" ::: "memory");

    float xr[PPT], yr[PPT], zr[PPT], dist[PPT];
    const int i0 = tid * PPT;
#pragma unroll
    for (int e = 0; e < PPT; e++) {
        xr[e] = sx[i0 + e]; yr[e] = sy[i0 + e]; zr[e] = sz[i0 + e];
        dist[e] = 1e10f;
    }
    float px = X[0], py = X[NPTS], pz = X[2 * NPTS];
    if (rank == 0 && tid == 0) {
        out[b * 3 * MCTR] = px;
        out[b * 3 * MCTR + MCTR] = py;
        out[b * 3 * MCTR + 2 * MCTR] = pz;
    }

    for (int step = 1; step < MCTR; step++) {
        const uint32_t parity = (uint32_t)((step - 1) & 1);
        float bv = -1.f; int bi = 0;
#pragma unroll
        for (int e = 0; e < PPT; e++) {
            float dx = fsub(xr[e], px), dy = fsub(yr[e], py), dz = fsub(zr[e], pz);
            float d  = fadd(fadd(fmul(dx, dx), fmul(dy, dy)), fmul(dz, dz));
            float nd = fminf(dist[e], d);
            dist[e] = nd;
            if (nd > bv) { bv = nd; bi = base + i0 + e; }
        }
#pragma unroll
        for (int off = 16; off > 0; off >>= 1) {
            float ov = __shfl_down_sync(0xffffffffu, bv, off);
            int   oi = __shfl_down_sync(0xffffffffu, bi, off);
            if (ov > bv || (ov == bv && oi < bi)) { bv = ov; bi = oi; }
        }
        if (lane == 0) { swv[w] = bv; swi[w] = bi; }
        __syncthreads();

        if (w == 0) {
            // block-level reduce of 8 warp candidates (lanes 0-7 hold the result)
            float v = (lane < 8) ? swv[lane] : -2.f;
            int   i = (lane < 8) ? swi[lane] : 0x7fffffff;
#pragma unroll
            for (int off = 4; off > 0; off >>= 1) {
                float ov = __shfl_xor_sync(0xffffffffu, v, off, 8);
                int   oi = __shfl_xor_sync(0xffffffffu, i, off, 8);
                if (ov > v || (ov == v && oi < i)) { v = ov; i = oi; }
            }
            if (lane == 0) {
                int li = i - base;
                float cx = sx[li], cy = sy[li], cz = sz[li];
                // push candidate to leader's slot[rank], then arrive leader's cand barrier
                uint32_t ra = mapa_u32(candBase + rank * 32u, 0u);
                st_cluster_b32(ra,      __float_as_uint(v));
                st_cluster_b32(ra + 4,  (uint32_t)i);
                st_cluster_b32(ra + 8,  __float_as_uint(cx));
                st_cluster_b32(ra + 12, __float_as_uint(cy));
                st_cluster_b32(ra + 16, __float_as_uint(cz));
                mbar_arrive_remote(candBarA, 0u);
            }
            if (rank == 0) {
                mbar_wait_cluster(candBarA, parity);
                int rl = lane & 7;
                const float* sp = &cand[rl][0];
                float v2 = sp[0];
                int   i2 = __float_as_int(sp[1]);
                float x2 = sp[2], y2 = sp[3], z2 = sp[4];
#pragma unroll
                for (int off = 4; off > 0; off >>= 1) {
                    float ov = __shfl_xor_sync(0xffffffffu, v2, off, 8);
                    int   oi = __shfl_xor_sync(0xffffffffu, i2, off, 8);
                    float ox = __shfl_xor_sync(0xffffffffu, x2, off, 8);
                    float oy = __shfl_xor_sync(0xffffffffu, y2, off, 8);
                    float oz = __shfl_xor_sync(0xffffffffu, z2, off, 8);
                    if (ov > v2 || (ov == v2 && oi < i2)) { v2 = ov; i2 = oi; x2 = ox; y2 = oy; z2 = oz; }
                }
                if (lane < FPS_CTAS) {
                    uint32_t ra = mapa_u32(resBase, (uint32_t)lane);
                    st_cluster_b32(ra,     __float_as_uint(x2));
                    st_cluster_b32(ra + 4, __float_as_uint(y2));
                    st_cluster_b32(ra + 8, __float_as_uint(z2));
                    mbar_arrive_remote(resBarA, (uint32_t)lane);
                }
                if (lane == 0) {
                    out[b * 3 * MCTR + step] = x2;
                    out[b * 3 * MCTR + MCTR + step] = y2;
                    out[b * 3 * MCTR + 2 * MCTR + step] = z2;
                }
            }
        }
        mbar_wait_cluster(resBarA, parity);
        px = res[0]; py = res[1]; pz = res[2];
    }
}

// ============ Ball query: warp/center, first-K ascending, early exit ============
__global__ void __launch_bounds__(256) ballquery_kernel(const float* __restrict__ xyz,
                                                        const float* __restrict__ out,
                                                        int K, float r2)
{
    int warp = (blockIdx.x * blockDim.x + threadIdx.x) >> 5;
    int lane = threadIdx.x & 31;
    int b = warp >> 11, m = warp & (MCTR - 1);
    const float* nx = out + b * 3 * MCTR;
    float cx = nx[m], cy = nx[MCTR + m], cz = nx[2 * MCTR + m];
    float sqc = fadd(fadd(fmul(cx, cx), fmul(cy, cy)), fmul(cz, cz));
    const float* X = xyz + (size_t)b * 3 * NPTS;

    int cnt = 0, firstIdx = 0;
    bool haveFirst = false;
    int* dst = g_bq + (size_t)warp * K;
    for (int base = 0; base < NPTS; base += 32) {
        int n = base + lane;
        float x = X[n], y = X[NPTS + n], z = X[2 * NPTS + n];
        float sqx = fadd(fadd(fmul(x, x), fmul(y, y)), fmul(z, z));
        float dot = fadd(fadd(fmul(cx, x), fmul(cy, y)), fmul(cz, z));
        float d2 = fsub(fadd(sqc, sqx), fmul(2.0f, dot));
        bool pred = d2 < r2;
        unsigned msk = __ballot_sync(0xffffffffu, pred);
        if (!haveFirst && msk) { firstIdx = base + __ffs(msk) - 1; haveFirst = true; }
        if (pred) {
            int pos = cnt + __popc(msk & ((1u << lane) - 1u));
            if (pos < K) dst[pos] = n;
        }
        cnt += __popc(msk);
        if (cnt >= K) break;
    }
    if (cnt < K) {
        int fill = haveFirst ? firstIdx : 0;
        for (int p = cnt + lane; p < K; p += 32) dst[p] = fill;
    }
}

// ============ Gather: build X0[c][col] = concat(gxyz - center, gfeat) ============
__global__ void __launch_bounds__(256) gather_kernel(const float* __restrict__ xyz,
                                                     const float* __restrict__ feat,
                                                     const float* __restrict__ out,
                                                     int logK, int cols)
{
    int col = blockIdx.x * 256 + threadIdx.x;
    int n  = g_bq[col];
    int mg = col >> logK;
    int b  = mg >> 11, m = mg & (MCTR - 1);
    const float* Xp = xyz + (size_t)b * 3 * NPTS;
    const float* C  = out + b * 3 * MCTR;
#pragma unroll
    for (int c = 0; c < 3; c++)
        g_bufA[(size_t)c * cols + col] = Xp[c * NPTS + n] - C[c * MCTR + m];
    const float* F = feat + (size_t)b * 64 * NPTS;
    for (int c = 0; c < 64; c++)
        g_bufA[(size_t)(3 + c) * cols + col] = F[(size_t)c * NPTS + n];
}

// ============ GEMM: Y[o][col] = W[o][:] . X'[:][col]  with X' = BN?relu(bn(X)):X
//              double-buffered smem pipeline, fused stat partials ============
template <bool BN>
__global__ void __launch_bounds__(256, 2) gemm_kernel(const float* __restrict__ W,
                                                      const float* __restrict__ X,
                                                      float* __restrict__ Y,
                                                      int Cin, int Cout, int ldc)
{
    __shared__ __align__(16) float Xs[2][16][132];
    __shared__ __align__(16) float Ws[2][16][132];
    __shared__ float sa[128], sb[128];
    const int tid = threadIdx.x;
    const int colBase = blockIdx.x * 128;

    if (BN && tid < Cin) { sa[tid] = g_a[tid]; sb[tid] = g_bb[tid]; }
    __syncthreads();

    const int nCh = (Cin + 15) >> 4;
    float rx[8], rw[8];

    auto loadT = [&](int c0, float* prx, float* prw) {
#pragma unroll
        for (int k = 0; k < 8; k++) {
            int idx = tid + k * 256;
            int j = idx & 127, kc = idx >> 7;
            int c = c0 + kc;
            float xv = 0.f;
            if (c < Cin) {
                xv = X[(size_t)c * ldc + colBase + j];
                if (BN) xv = fmaxf(0.f, fmaf(sa[c], xv, sb[c]));
            }
            prx[k] = xv;
            prw[k] = (j < Cout && c < Cin) ? W[j * Cin + c] : 0.f;
        }
    };
    auto storeT = [&](int buf, const float* prx, const float* prw) {
#pragma unroll
        for (int k = 0; k < 8; k++) {
            int idx = tid + k * 256;
            int j = idx & 127, kc = idx >> 7;
            Xs[buf][kc][j] = prx[k];
            Ws[buf][kc][j] = prw[k];
        }
    };

    loadT(0, rx, rw);
    storeT(0, rx, rw);
    __syncthreads();

    float acc[8][8] = {};
    const int j4 = (tid & 15) * 4, o8 = (tid >> 4) * 8;

    for (int ch = 0; ch < nCh; ch++) {
        const int buf = ch & 1;
        if (ch + 1 < nCh) loadT((ch + 1) * 16, rx, rw);
#pragma unroll
        for (int kc = 0; kc < 16; kc++) {
            float4 xa = *(float4*)&Xs[buf][kc][j4];
            float4 xb = *(float4*)&Xs[buf][kc][j4 + 64];
            float4 wa = *(float4*)&Ws[buf][kc][o8];
            float4 wb = *(float4*)&Ws[buf][kc][o8 + 4];
            float xv[8] = {xa.x, xa.y, xa.z, xa.w, xb.x, xb.y, xb.z, xb.w};
            float wv[8] = {wa.x, wa.y, wa.z, wa.w, wb.x, wb.y, wb.z, wb.w};
#pragma unroll
            for (int i = 0; i < 8; i++)
#pragma unroll
                for (int j = 0; j < 8; j++) acc[i][j] = fmaf(wv[i], xv[j], acc[i][j]);
        }
        if (ch + 1 < nCh) {
            __syncthreads();
            storeT(buf ^ 1, rx, rw);
            __syncthreads();
        }
    }

    const int o0 = o8;
#pragma unroll
    for (int i = 0; i < 8; i++) {
        int o = o0 + i;
        if (o < Cout) {
            float* dst = Y + (size_t)o * ldc + colBase + j4;
            *(float4*)dst        = make_float4(acc[i][0], acc[i][1], acc[i][2], acc[i][3]);
            *(float4*)(dst + 64) = make_float4(acc[i][4], acc[i][5], acc[i][6], acc[i][7]);
        }
    }
    float s[8], q[8];
#pragma unroll
    for (int i = 0; i < 8; i++) {
        float ts = 0.f, tq = 0.f;
#pragma unroll
        for (int j = 0; j < 8; j++) { ts += acc[i][j]; tq += acc[i][j] * acc[i][j]; }
        s[i] = ts; q[i] = tq;
    }
#pragma unroll
    for (int off = 8; off > 0; off >>= 1)
#pragma unroll
        for (int i = 0; i < 8; i++) {
            s[i] += __shfl_down_sync(0xffffffffu, s[i], off, 16);
            q[i] += __shfl_down_sync(0xffffffffu, q[i], off, 16);
        }
    if ((tid & 15) == 0)
#pragma unroll
        for (int i = 0; i < 8; i++)
            g_part[(size_t)blockIdx.x * 128 + o0 + i] = make_float2(s[i], q[i]);
}

// ============ deterministic stats reduce -> BN scale/shift ============
__global__ void __launch_bounds__(256) reduce_stats_kernel(const float* __restrict__ gam,
                                                           const float* __restrict__ bet,
                                                           int R, float inv_n)
{
    __shared__ float ss[256], sq[256];
    int c = blockIdx.x, tid = threadIdx.x;
    float s = 0.f, q = 0.f;
    for (int r = tid; r < R; r += 256) {
        float2 v = g_part[(size_t)r * 128 + c];
        s += v.x; q += v.y;
    }
    ss[tid] = s; sq[tid] = q;
    __syncthreads();
    for (int off = 128; off > 0; off >>= 1) {
        if (tid < off) { ss[tid] += ss[tid + off]; sq[tid] += sq[tid + off]; }
        __syncthreads();
    }
    if (tid == 0) {
        float mu = ss[0] * inv_n;
        float var = sq[0] * inv_n - mu * mu;
        if (var < 0.f) var = 0.f;
        float a = gam[c] * rsqrtf(var + 1e-5f);
        g_a[c] = a;
        g_bb[c] = bet[c] - mu * a;
    }
}

// ============ BN + ReLU + max over K -> output features ============
__global__ void __launch_bounds__(1024) maxpool_kernel(const float* __restrict__ Y,
                                                       float* __restrict__ out,
                                                       int K, int chanOff, int ldc)
{
    int gw = (blockIdx.x * 1024 + threadIdx.x) >> 5;
    int lane = threadIdx.x & 31;
    int o = gw & 127;
    int mg = gw >> 7;
    int b = mg >> 11, m = mg & (MCTR - 1);
    float a = g_a[o], bb = g_bb[o];
    const float* src = Y + (size_t)o * ldc + (size_t)mg * K;
    float v = 0.f;
    for (int k = lane; k < K; k += 32)
        v = fmaxf(v, fmaf(a, src[k], bb));
#pragma unroll
    for (int off = 16; off > 0; off >>= 1)
        v = fmaxf(v, __shfl_xor_sync(0xffffffffu, v, off));
    if (lane == 0)
        out[24576 + ((size_t)(b * 256 + chanOff + o)) * MCTR + m] = v;
}

// ==================== host side ====================
extern "C" void kernel_launch(void* const* d_in, const int* in_sizes, int n_in,
                              void* d_out, int out_size)
{
    const float* xyz  = (const float*)d_in[0];
    const float* feat = (const float*)d_in[1];
    float* out = (float*)d_out;

    fps_cluster_kernel<<<4 * FPS_CTAS, FPS_THREADS>>>(xyz, out);

    const int KS[2] = {32, 64};
    const float R2[2] = {(float)(0.2 * 0.2), (float)(0.4 * 0.4)};
    const int CH[2][3] = {{64, 64, 128}, {64, 96, 128}};

    for (int s = 0; s < 2; s++) {
        int K = KS[s];
        int logK = (K == 32) ? 5 : 6;
        int cols = 4 * MCTR * K;            // 262144 or 524288
        int nBlk = cols / 128;
        float inv_n = 1.0f / (float)cols;

        ballquery_kernel<<<1024, 256>>>(xyz, out, K, R2[s]);
        gather_kernel<<<cols / 256, 256>>>(xyz, feat, out, logK, cols);

        const float* Wl[3], *Gl[3], *Bl[3];
        for (int l = 0; l < 3; l++) {
            Wl[l] = (const float*)d_in[2 + s * 9 + l * 3 + 0];
            Gl[l] = (const float*)d_in[2 + s * 9 + l * 3 + 1];
            Bl[l] = (const float*)d_in[2 + s * 9 + l * 3 + 2];
        }
        float *pA, *pB;
        cudaGetSymbolAddress((void**)&pA, g_bufA);
        cudaGetSymbolAddress((void**)&pB, g_bufB);

        // L0: A(67 raw) -> B(c0)
        gemm_kernel<false><<<nBlk, 256>>>(Wl[0], pA, pB, 67, CH[s][0], cols);
        reduce_stats_kernel<<<CH[s][0], 256>>>(Gl[0], Bl[0], nBlk, inv_n);
        // L1: B (bn+relu fused on load) -> A(c1)
        gemm_kernel<true><<<nBlk, 256>>>(Wl[1], pB, pA, CH[s][0], CH[s][1], cols);
        reduce_stats_kernel<<<CH[s][1], 256>>>(Gl[1], Bl[1], nBlk, inv_n);
        // L2: A (bn+relu fused on load) -> B(128)
        gemm_kernel<true><<<nBlk, 256>>>(Wl[2], pA, pB, CH[s][1], CH[s][2], cols);
        reduce_stats_kernel<<<CH[s][2], 256>>>(Gl[2], Bl[2], nBlk, inv_n);
        maxpool_kernel<<<(4 * MCTR * 128) / 32, 1024>>>(pB, out, K, s * 128, cols);
    }
}

// round 11
// speedup vs baseline: 1.5332x; 1.1295x over previous
#include <cuda_runtime.h>
#include <cstdint>

#define NPTS 16384
#define MCTR 2048
#define FPS_CTAS 8
#define FPS_THREADS 256
#define SLICE (NPTS / FPS_CTAS)
#define PPT (SLICE / FPS_THREADS)

// ---------------- device scratch ----------------
__device__ int    g_bq[4 * MCTR * 64];
__device__ float  g_bufA[50331648];   // up to 96 ch x 524288 cols
__device__ float  g_bufB[67108864];   // up to 128 ch x 524288 cols
__device__ float2 g_part[4096 * 128];
__device__ float  g_a[128];
__device__ float  g_bb[128];

__device__ __forceinline__ float fadd(float a, float b) { return __fadd_rn(a, b); }
__device__ __forceinline__ float fmul(float a, float b) { return __fmul_rn(a, b); }
__device__ __forceinline__ float fsub(float a, float b) { return __fsub_rn(a, b); }

// ---- mbarrier helpers (cluster scope) ----
__device__ __forceinline__ void mbar_init(uint32_t addr, uint32_t count) {
    asm volatile("mbarrier.init.shared.b64 [%0], %1;" :: "r"(addr), "r"(count) : "memory");
}
__device__ __forceinline__ void mbar_wait_cluster(uint32_t addr, uint32_t parity) {
    asm volatile(
        "{\n\t.reg .pred P;\n\t"
        "WAITL_%=:\n\t"
        "mbarrier.try_wait.parity.acquire.cluster.shared::cta.b64 P, [%0], %1, 0x989680;\n\t"
        "@P bra.uni DONEL_%=;\n\t"
        "bra.uni WAITL_%=;\n\t"
        "DONEL_%=:\n\t}"
        :: "r"(addr), "r"(parity) : "memory");
}
__device__ __forceinline__ void mbar_arrive_remote(uint32_t laddr, uint32_t rank) {
    asm volatile(
        "{\n\t.reg .b32 ra;\n\t"
        "mapa.shared::cluster.u32 ra, %0, %1;\n\t"
        "mbarrier.arrive.shared::cluster.b64 _, [ra];\n\t}"
        :: "r"(laddr), "r"(rank) : "memory");
}
__device__ __forceinline__ uint32_t mapa_u32(uint32_t laddr, uint32_t rank) {
    uint32_t ra;
    asm volatile("mapa.shared::cluster.u32 %0, %1, %2;" : "=r"(ra) : "r"(laddr), "r"(rank));
    return ra;
}
__device__ __forceinline__ void st_cluster_b32(uint32_t addr, uint32_t v) {
    asm volatile("st.shared::cluster.b32 [%0], %1;" :: "r"(addr), "r"(v) : "memory");
}

// ============ FPS: 8-CTA cluster per batch, mbarrier leader-reduce exchange ============
// (known-good version: bit-exact, passed at 4376us)
__global__ __launch_bounds__(FPS_THREADS) __cluster_dims__(FPS_CTAS, 1, 1)
void fps_cluster_kernel(const float* __restrict__ xyz, float* __restrict__ out)
{
    __shared__ float sx[SLICE], sy[SLICE], sz[SLICE];
    __shared__ float swv[8];
    __shared__ int   swi[8];
    __shared__ __align__(16) float cand[8][8];    // leader: per-rank {v,i,x,y,z}
    __shared__ __align__(16) float res[4];        // winner {x,y,z}
    __shared__ __align__(8) unsigned long long candBar, resBar;

    const int tid = threadIdx.x;
    const int lane = tid & 31, w = tid >> 5;
    const int b = blockIdx.x / FPS_CTAS;
    uint32_t rank;
    asm("mov.u32 %0, %%cluster_ctarank;" : "=r"(rank));
    const float* X = xyz + (size_t)b * 3 * NPTS;
    const int base = rank * SLICE;

    for (int i = tid; i < SLICE; i += FPS_THREADS) {
        sx[i] = X[base + i];
        sy[i] = X[NPTS + base + i];
        sz[i] = X[2 * NPTS + base + i];
    }
    const uint32_t candBase = (uint32_t)__cvta_generic_to_shared(&cand[0][0]);
    const uint32_t resBase  = (uint32_t)__cvta_generic_to_shared(&res[0]);
    const uint32_t candBarA = (uint32_t)__cvta_generic_to_shared(&candBar);
    const uint32_t resBarA  = (uint32_t)__cvta_generic_to_shared(&resBar);
    if (tid == 0) {
        mbar_init(candBarA, FPS_CTAS);
        mbar_init(resBarA, 1);
    }
    __syncthreads();
    asm volatile("barrier.cluster.arrive.aligned;" ::: "memory");
    asm volatile("barrier.cluster.wait.aligned;" ::: "memory");

    float xr[PPT], yr[PPT], zr[PPT], dist[PPT];
    const int i0 = tid * PPT;
#pragma unroll
    for (int e = 0; e < PPT; e++) {
        xr[e] = sx[i0 + e]; yr[e] = sy[i0 + e]; zr[e] = sz[i0 + e];
        dist[e] = 1e10f;
    }
    float px = X[0], py = X[NPTS], pz = X[2 * NPTS];
    if (rank == 0 && tid == 0) {
        out[b * 3 * MCTR] = px;
        out[b * 3 * MCTR + MCTR] = py;
        out[b * 3 * MCTR + 2 * MCTR] = pz;
    }

    for (int step = 1; step < MCTR; step++) {
        const uint32_t parity = (uint32_t)((step - 1) & 1);
        float bv = -1.f; int bi = 0;
#pragma unroll
        for (int e = 0; e < PPT; e++) {
            float dx = fsub(xr[e], px), dy = fsub(yr[e], py), dz = fsub(zr[e], pz);
            float d  = fadd(fadd(fmul(dx, dx), fmul(dy, dy)), fmul(dz, dz));
            float nd = fminf(dist[e], d);
            dist[e] = nd;
            if (nd > bv) { bv = nd; bi = base + i0 + e; }
        }
#pragma unroll
        for (int off = 16; off > 0; off >>= 1) {
            float ov = __shfl_down_sync(0xffffffffu, bv, off);
            int   oi = __shfl_down_sync(0xffffffffu, bi, off);
            if (ov > bv || (ov == bv && oi < bi)) { bv = ov; bi = oi; }
        }
        if (lane == 0) { swv[w] = bv; swi[w] = bi; }
        __syncthreads();

        if (w == 0) {
            float v = (lane < 8) ? swv[lane] : -2.f;
            int   i = (lane < 8) ? swi[lane] : 0x7fffffff;
#pragma unroll
            for (int off = 4; off > 0; off >>= 1) {
                float ov = __shfl_xor_sync(0xffffffffu, v, off, 8);
                int   oi = __shfl_xor_sync(0xffffffffu, i, off, 8);
                if (ov > v || (ov == v && oi < i)) { v = ov; i = oi; }
            }
            if (lane == 0) {
                int li = i - base;
                float cx = sx[li], cy = sy[li], cz = sz[li];
                uint32_t ra = mapa_u32(candBase + rank * 32u, 0u);
                st_cluster_b32(ra,      __float_as_uint(v));
                st_cluster_b32(ra + 4,  (uint32_t)i);
                st_cluster_b32(ra + 8,  __float_as_uint(cx));
                st_cluster_b32(ra + 12, __float_as_uint(cy));
                st_cluster_b32(ra + 16, __float_as_uint(cz));
                mbar_arrive_remote(candBarA, 0u);
            }
            if (rank == 0) {
                mbar_wait_cluster(candBarA, parity);
                int rl = lane & 7;
                const float* sp = &cand[rl][0];
                float v2 = sp[0];
                int   i2 = __float_as_int(sp[1]);
                float x2 = sp[2], y2 = sp[3], z2 = sp[4];
#pragma unroll
                for (int off = 4; off > 0; off >>= 1) {
                    float ov = __shfl_xor_sync(0xffffffffu, v2, off, 8);
                    int   oi = __shfl_xor_sync(0xffffffffu, i2, off, 8);
                    float ox = __shfl_xor_sync(0xffffffffu, x2, off, 8);
                    float oy = __shfl_xor_sync(0xffffffffu, y2, off, 8);
                    float oz = __shfl_xor_sync(0xffffffffu, z2, off, 8);
                    if (ov > v2 || (ov == v2 && oi < i2)) { v2 = ov; i2 = oi; x2 = ox; y2 = oy; z2 = oz; }
                }
                if (lane < FPS_CTAS) {
                    uint32_t ra = mapa_u32(resBase, (uint32_t)lane);
                    st_cluster_b32(ra,     __float_as_uint(x2));
                    st_cluster_b32(ra + 4, __float_as_uint(y2));
                    st_cluster_b32(ra + 8, __float_as_uint(z2));
                    mbar_arrive_remote(resBarA, (uint32_t)lane);
                }
                if (lane == 0) {
                    out[b * 3 * MCTR + step] = x2;
                    out[b * 3 * MCTR + MCTR + step] = y2;
                    out[b * 3 * MCTR + 2 * MCTR + step] = z2;
                }
            }
        }
        mbar_wait_cluster(resBarA, parity);
        px = res[0]; py = res[1]; pz = res[2];
    }
}

// ============ Ball query: warp/center, first-K ascending, early exit ============
__global__ void __launch_bounds__(256) ballquery_kernel(const float* __restrict__ xyz,
                                                        const float* __restrict__ out,
                                                        int K, float r2)
{
    int warp = (blockIdx.x * blockDim.x + threadIdx.x) >> 5;
    int lane = threadIdx.x & 31;
    int b = warp >> 11, m = warp & (MCTR - 1);
    const float* nx = out + b * 3 * MCTR;
    float cx = nx[m], cy = nx[MCTR + m], cz = nx[2 * MCTR + m];
    float sqc = fadd(fadd(fmul(cx, cx), fmul(cy, cy)), fmul(cz, cz));
    const float* X = xyz + (size_t)b * 3 * NPTS;

    int cnt = 0, firstIdx = 0;
    bool haveFirst = false;
    int* dst = g_bq + (size_t)warp * K;
    for (int base = 0; base < NPTS; base += 32) {
        int n = base + lane;
        float x = X[n], y = X[NPTS + n], z = X[2 * NPTS + n];
        float sqx = fadd(fadd(fmul(x, x), fmul(y, y)), fmul(z, z));
        float dot = fadd(fadd(fmul(cx, x), fmul(cy, y)), fmul(cz, z));
        float d2 = fsub(fadd(sqc, sqx), fmul(2.0f, dot));
        bool pred = d2 < r2;
        unsigned msk = __ballot_sync(0xffffffffu, pred);
        if (!haveFirst && msk) { firstIdx = base + __ffs(msk) - 1; haveFirst = true; }
        if (pred) {
            int pos = cnt + __popc(msk & ((1u << lane) - 1u));
            if (pos < K) dst[pos] = n;
        }
        cnt += __popc(msk);
        if (cnt >= K) break;
    }
    if (cnt < K) {
        int fill = haveFirst ? firstIdx : 0;
        for (int p = cnt + lane; p < K; p += 32) dst[p] = fill;
    }
}

// ============ GEMM: Y[o][col] = W[o][:] . X'[:][col]
//   Whole X and W tiles resident in (dynamic) smem; single sync; no pipeline.
//   GATHER: X built from xyz/feat/g_bq/centers (layer 0).
//   BN: X = relu(bn(Xin)) fused on load (layers 1,2).
//   Fused deterministic per-block BN stat partials in epilogue. ============
template <bool BN, bool GATHER>
__global__ void __launch_bounds__(256) gemm_kernel(const float* __restrict__ W,
                                                   const float* __restrict__ X,
                                                   float* __restrict__ Y,
                                                   int Cin, int CinPad, int Cout, int ldc,
                                                   int logK,
                                                   const float* __restrict__ xyz,
                                                   const float* __restrict__ feat,
                                                   const float* __restrict__ ctr)
{
    extern __shared__ __align__(16) float dsm[];
    float* Xs = dsm;                      // [CinPad][132]
    float* Ws = dsm + (size_t)CinPad * 132;  // [CinPad][132]
    __shared__ float sa[128], sb[128];
    __shared__ int   sidx[128];
    __shared__ float sctr[3][128];

    const int tid = threadIdx.x;
    const int colBase = blockIdx.x * 128;

    if (BN && tid < Cin) { sa[tid] = g_a[tid]; sb[tid] = g_bb[tid]; }
    if (GATHER && tid < 128) {
        int col = colBase + tid;
        sidx[tid] = g_bq[col];
        int mg = col >> logK;
        int bb_ = mg >> 11, m = mg & (MCTR - 1);
#pragma unroll
        for (int d = 0; d < 3; d++)
            sctr[d][tid] = ctr[bb_ * 3 * MCTR + d * MCTR + m];
    }
    __syncthreads();

    const int total = CinPad * 128;
    if (GATHER) {
        const int bb_ = colBase >> (logK + 11);
        const float* Xp = xyz + (size_t)bb_ * 3 * NPTS;
        const float* Fp = feat + (size_t)bb_ * 64 * NPTS;
        for (int t = tid; t < total; t += 256) {
            int j = t & 127, kc = t >> 7;
            int n = sidx[j];
            float v = 0.f;
            if (kc < 3)       v = Xp[kc * NPTS + n] - sctr[kc][j];
            else if (kc < 67) v = Fp[(kc - 3) * NPTS + n];
            Xs[kc * 132 + j] = v;
            Ws[kc * 132 + j] = (j < Cout && kc < Cin) ? W[j * Cin + kc] : 0.f;
        }
    } else {
        for (int t = tid; t < total; t += 256) {
            int j = t & 127, kc = t >> 7;
            float v = 0.f;
            if (kc < Cin) {
                v = X[(size_t)kc * ldc + colBase + j];
                if (BN) v = fmaxf(0.f, fmaf(sa[kc], v, sb[kc]));
            }
            Xs[kc * 132 + j] = v;
            Ws[kc * 132 + j] = (j < Cout && kc < Cin) ? W[j * Cin + kc] : 0.f;
        }
    }
    __syncthreads();

    float acc[8][8] = {};
    const int j4 = (tid & 15) * 4, o8 = (tid >> 4) * 8;

#pragma unroll 4
    for (int kc = 0; kc < CinPad; kc++) {
        const float* xr = Xs + kc * 132;
        const float* wr = Ws + kc * 132;
        float4 xa = *(const float4*)(xr + j4);
        float4 xb = *(const float4*)(xr + j4 + 64);
        float4 wa = *(const float4*)(wr + o8);
        float4 wb = *(const float4*)(wr + o8 + 4);
        float xv[8] = {xa.x, xa.y, xa.z, xa.w, xb.x, xb.y, xb.z, xb.w};
        float wv[8] = {wa.x, wa.y, wa.z, wa.w, wb.x, wb.y, wb.z, wb.w};
#pragma unroll
        for (int i = 0; i < 8; i++)
#pragma unroll
            for (int j = 0; j < 8; j++) acc[i][j] = fmaf(wv[i], xv[j], acc[i][j]);
    }

    const int o0 = o8;
#pragma unroll
    for (int i = 0; i < 8; i++) {
        int o = o0 + i;
        if (o < Cout) {
            float* dst = Y + (size_t)o * ldc + colBase + j4;
            *(float4*)dst        = make_float4(acc[i][0], acc[i][1], acc[i][2], acc[i][3]);
            *(float4*)(dst + 64) = make_float4(acc[i][4], acc[i][5], acc[i][6], acc[i][7]);
        }
    }
    float s[8], q[8];
#pragma unroll
    for (int i = 0; i < 8; i++) {
        float ts = 0.f, tq = 0.f;
#pragma unroll
        for (int j = 0; j < 8; j++) { ts += acc[i][j]; tq += acc[i][j] * acc[i][j]; }
        s[i] = ts; q[i] = tq;
    }
#pragma unroll
    for (int off = 8; off > 0; off >>= 1)
#pragma unroll
        for (int i = 0; i < 8; i++) {
            s[i] += __shfl_down_sync(0xffffffffu, s[i], off, 16);
            q[i] += __shfl_down_sync(0xffffffffu, q[i], off, 16);
        }
    if ((tid & 15) == 0)
#pragma unroll
        for (int i = 0; i < 8; i++)
            g_part[(size_t)blockIdx.x * 128 + o0 + i] = make_float2(s[i], q[i]);
}

// ============ deterministic stats reduce -> BN scale/shift ============
__global__ void __launch_bounds__(256) reduce_stats_kernel(const float* __restrict__ gam,
                                                           const float* __restrict__ bet,
                                                           int R, float inv_n)
{
    __shared__ float ss[256], sq[256];
    int c = blockIdx.x, tid = threadIdx.x;
    float s = 0.f, q = 0.f;
    for (int r = tid; r < R; r += 256) {
        float2 v = g_part[(size_t)r * 128 + c];
        s += v.x; q += v.y;
    }
    ss[tid] = s; sq[tid] = q;
    __syncthreads();
    for (int off = 128; off > 0; off >>= 1) {
        if (tid < off) { ss[tid] += ss[tid + off]; sq[tid] += sq[tid + off]; }
        __syncthreads();
    }
    if (tid == 0) {
        float mu = ss[0] * inv_n;
        float var = sq[0] * inv_n - mu * mu;
        if (var < 0.f) var = 0.f;
        float a = gam[c] * rsqrtf(var + 1e-5f);
        g_a[c] = a;
        g_bb[c] = bet[c] - mu * a;
    }
}

// ============ BN + ReLU + max over K -> output features ============
__global__ void __launch_bounds__(1024) maxpool_kernel(const float* __restrict__ Y,
                                                       float* __restrict__ out,
                                                       int K, int chanOff, int ldc)
{
    int gw = (blockIdx.x * 1024 + threadIdx.x) >> 5;
    int lane = threadIdx.x & 31;
    int o = gw & 127;
    int mg = gw >> 7;
    int b = mg >> 11, m = mg & (MCTR - 1);
    float a = g_a[o], bb = g_bb[o];
    const float* src = Y + (size_t)o * ldc + (size_t)mg * K;
    float v = 0.f;
    for (int k = lane; k < K; k += 32)
        v = fmaxf(v, fmaf(a, src[k], bb));
#pragma unroll
    for (int off = 16; off > 0; off >>= 1)
        v = fmaxf(v, __shfl_xor_sync(0xffffffffu, v, off));
    if (lane == 0)
        out[24576 + ((size_t)(b * 256 + chanOff + o)) * MCTR + m] = v;
}

// ==================== host side ====================
extern "C" void kernel_launch(void* const* d_in, const int* in_sizes, int n_in,
                              void* d_out, int out_size)
{
    const float* xyz  = (const float*)d_in[0];
    const float* feat = (const float*)d_in[1];
    float* out = (float*)d_out;

    fps_cluster_kernel<<<4 * FPS_CTAS, FPS_THREADS>>>(xyz, out);

    const int KS[2] = {32, 64};
    const float R2[2] = {(float)(0.2 * 0.2), (float)(0.4 * 0.4)};
    const int CH[2][3] = {{64, 64, 128}, {64, 96, 128}};

    // allow large dynamic smem for both instantiations (idempotent)
    cudaFuncSetAttribute(gemm_kernel<false, true>,
                         cudaFuncAttributeMaxDynamicSharedMemorySize, 68 * 132 * 2 * 4);
    cudaFuncSetAttribute(gemm_kernel<true, false>,
                         cudaFuncAttributeMaxDynamicSharedMemorySize, 96 * 132 * 2 * 4);

    for (int s = 0; s < 2; s++) {
        int K = KS[s];
        int logK = (K == 32) ? 5 : 6;
        int cols = 4 * MCTR * K;            // 262144 or 524288
        int nBlk = cols / 128;
        float inv_n = 1.0f / (float)cols;

        ballquery_kernel<<<1024, 256>>>(xyz, out, K, R2[s]);

        const float* Wl[3], *Gl[3], *Bl[3];
        for (int l = 0; l < 3; l++) {
            Wl[l] = (const float*)d_in[2 + s * 9 + l * 3 + 0];
            Gl[l] = (const float*)d_in[2 + s * 9 + l * 3 + 1];
            Bl[l] = (const float*)d_in[2 + s * 9 + l * 3 + 2];
        }
        float *pA, *pB;
        cudaGetSymbolAddress((void**)&pA, g_bufA);
        cudaGetSymbolAddress((void**)&pB, g_bufB);

        int c0 = CH[s][0], c1 = CH[s][1], c2 = CH[s][2];

        // L0: gather(xyz,feat) fused -> B(c0).  Cin=67, CinPad=68.
        gemm_kernel<false, true><<<nBlk, 256, 68 * 132 * 2 * 4>>>(
            Wl[0], nullptr, pB, 67, 68, c0, cols, logK, xyz, feat, out);
        reduce_stats_kernel<<<c0, 256>>>(Gl[0], Bl[0], nBlk, inv_n);

        // L1: B (bn+relu fused) -> A(c1).
        gemm_kernel<true, false><<<nBlk, 256, c0 * 132 * 2 * 4>>>(
            Wl[1], pB, pA, c0, c0, c1, cols, logK, xyz, feat, out);
        reduce_stats_kernel<<<c1, 256>>>(Gl[1], Bl[1], nBlk, inv_n);

        // L2: A (bn+relu fused) -> B(128).
        gemm_kernel<true, false><<<nBlk, 256, c1 * 132 * 2 * 4>>>(
            Wl[2], pA, pB, c1, c1, c2, cols, logK, xyz, feat, out);
        reduce_stats_kernel<<<c2, 256>>>(Gl[2], Bl[2], nBlk, inv_n);

        maxpool_kernel<<<(4 * MCTR * 128) / 32, 1024>>>(pB, out, K, s * 128, cols);
    }
}